// round 15
// baseline (speedup 1.0000x reference)
#include <cuda_runtime.h>
#include <cuda_bf16.h>

// Soft local histogram, R=5, bandwidth=0.5.
// Input/output: (4, 8, 3, 256, 256) fp32 -> 96 images of 256x256.
// out[y,x] = sum_{di,dj in [-2,2]} max(0, 1 - 2*|x[y+di,x+dj] - x[y,x]|)
// for y,x in [2, 254); zero on the 2-pixel border.
//
// Hybrid packed/scalar taps: FFMA2 only where the pair is FREE (a-pairs come
// straight from SMEM b64/b128 loads; nc2 pairs built once):
//   d2      = fma.rn.f32x2(a_pair, {2,2}, nc2_pair)   // 1 issue / 2 taps
//   w_lo/hi = __saturatef(fma(|d|, -1, 1))            // FFMA.SAT-imm, rt=1
//   acc_lo/hi += via scalar FFMA-imm (rt=1)           // no pack MOV, no FFMA2 rt=2
// 5 issues per 2 taps (scalar: 6; full-packed R14: ~7 incl. MOVs).
// Centers computed naturally: fma(c,2,-2c) == 0 -> w == 1 exactly; acc from 0.

#define IMG_H 256
#define IMG_W 256
#define TX 8            // threads in x; each covers PX=4 pixels -> 32 wide
#define TYB 32
#define PX 4
#define PY 2
#define BW 32
#define BH (TYB * PY)   // 64 output rows per block
#define TILE_H (BH + 4) // 68
#define TILE_W 56
#define NF4 12
#define NLOAD (TILE_H * NF4)   // 816

typedef unsigned long long u64;

__device__ __forceinline__ u64 ffma2(u64 a, u64 b, u64 c) {
    u64 d;
    asm("fma.rn.f32x2 %0, %1, %2, %3;" : "=l"(d) : "l"(a), "l"(b), "l"(c));
    return d;
}
__device__ __forceinline__ u64 fmul2(u64 a, u64 b) {
    u64 d;
    asm("mul.rn.f32x2 %0, %1, %2;" : "=l"(d) : "l"(a), "l"(b));
    return d;
}
__device__ __forceinline__ u64 pack2(float lo, float hi) {
    u64 r;
    asm("mov.b64 %0, {%1, %2};" : "=l"(r) : "f"(lo), "f"(hi));
    return r;
}
__device__ __forceinline__ void unpack2(u64 v, float& lo, float& hi) {
    asm("mov.b64 {%0, %1}, %2;" : "=f"(lo), "=f"(hi) : "l"(v));
}

#define TWO2  0x4000000040000000ull   // {2.0f, 2.0f}
#define NTWO2 0xC0000000C0000000ull   // {-2.0f, -2.0f}

__global__ __launch_bounds__(TX * TYB, 6) void soft_hist_kernel(
    const float* __restrict__ in, float* __restrict__ out)
{
    __shared__ float tile[TILE_H][TILE_W];

    const int img = blockIdx.z;
    const float* im = in + (size_t)img * IMG_H * IMG_W;
    float* om = out + (size_t)img * IMG_H * IMG_W;

    const int x0 = blockIdx.x * BW;
    const int y0 = blockIdx.y * BH;
    const int tx = threadIdx.x;
    const int ty = threadIdx.y;
    const int tid = ty * TX + tx;

    // 48-float aligned load window from base_x; smem col s = g - base_x + 4.
    // Clamped rows/cols only feed outputs in the forced-zero border.
    int base_x = x0 - 8;
    if (base_x < 0) base_x = 0;
    if (base_x > IMG_W - 48) base_x = IMG_W - 48;   // 208

    for (int idx = tid; idx < NLOAD; idx += TX * TYB) {
        int ly = idx / NF4;
        int lf = idx - ly * NF4;
        int gy = min(max(y0 + ly - 2, 0), IMG_H - 1);
        float4 v = *reinterpret_cast<const float4*>(im + gy * IMG_W + base_x + lf * 4);
        *reinterpret_cast<float4*>(&tile[ly][4 + lf * 4]) = v;
    }
    __syncthreads();

    // Thread outputs: cols gxb + p (p=0..3), rows y0 + ty*PY + k (k=0..1).
    const int scol0 = (x0 + PX * tx) - base_x + 4;
    const int rbase = ty * PY;

    // Centers: LDS.128 -> two aligned pairs -> nc2 pairs via mul.f32x2.
    u64 nc2p[PY][2];         // [k][h]: (-2c_{2h}, -2c_{2h+1})
    float acc[PY][PX];       // scalar 2*sum accumulators (center included)
    #pragma unroll
    for (int k = 0; k < PY; k++) {
        ulonglong2 c = *reinterpret_cast<const ulonglong2*>(&tile[rbase + k + 2][scol0]);
        nc2p[k][0] = fmul2(c.x, NTWO2);
        nc2p[k][1] = fmul2(c.y, NTWO2);
        #pragma unroll
        for (int p = 0; p < PX; p++) acc[k][p] = 0.0f;
    }

    // Slide over PY+4 tap rows. Row window a[0..7], a[i] at col scol0-2+i.
    // Packed pairs: P[i] = (a[i], a[i+1]).  Pair h (p=2h,2h+1), tap j uses
    // P[j + 2h].  Even P direct from b64/b128 loads, odd P packed (3 MOVs).
    #pragma unroll
    for (int ry = 0; ry < PY + 4; ry++) {
        const float* row = &tile[rbase + ry][0];
        u64 P[7];
        P[0] = *reinterpret_cast<const u64*>(row + scol0 - 2);          // (a0,a1)
        {
            ulonglong2 md = *reinterpret_cast<const ulonglong2*>(row + scol0);
            P[2] = md.x;                                                // (a2,a3)
            P[4] = md.y;                                                // (a4,a5)
        }
        P[6] = *reinterpret_cast<const u64*>(row + scol0 + 4);          // (a6,a7)
        {
            float a0, a1, a2, a3, a4, a5, a6, a7;
            unpack2(P[0], a0, a1);
            unpack2(P[2], a2, a3);
            unpack2(P[4], a4, a5);
            unpack2(P[6], a6, a7);
            P[1] = pack2(a1, a2);
            P[3] = pack2(a3, a4);
            P[5] = pack2(a5, a6);
        }
        #pragma unroll
        for (int k = 0; k < PY; k++) {
            if (ry >= k && ry <= k + 4) {
                #pragma unroll
                for (int h = 0; h < 2; h++) {
                    #pragma unroll
                    for (int j = 0; j < 5; j++) {
                        u64 d2 = ffma2(P[j + 2 * h], TWO2, nc2p[k][h]);   // 2 taps
                        float dlo, dhi;
                        unpack2(d2, dlo, dhi);
                        float wlo = __saturatef(fmaf(fabsf(dlo), -1.0f, 1.0f));
                        float whi = __saturatef(fmaf(fabsf(dhi), -1.0f, 1.0f));
                        acc[k][2 * h + 0] = fmaf(wlo, 2.0f, acc[k][2 * h + 0]);
                        acc[k][2 * h + 1] = fmaf(whi, 2.0f, acc[k][2 * h + 1]);
                    }
                }
            }
        }
    }

    // Epilogue: border select + 0.5x scale, one STG.128 per output row.
    const int gxb = x0 + PX * tx;
    #pragma unroll
    for (int k = 0; k < PY; k++) {
        int gy = y0 + rbase + k;
        bool yin = (gy >= 2) && (gy < IMG_H - 2);
        float4 v;
        v.x = (yin && gxb + 0 >= 2 && gxb + 0 < IMG_W - 2) ? 0.5f * acc[k][0] : 0.0f;
        v.y = (yin && gxb + 1 >= 2 && gxb + 1 < IMG_W - 2) ? 0.5f * acc[k][1] : 0.0f;
        v.z = (yin && gxb + 2 >= 2 && gxb + 2 < IMG_W - 2) ? 0.5f * acc[k][2] : 0.0f;
        v.w = (yin && gxb + 3 >= 2 && gxb + 3 < IMG_W - 2) ? 0.5f * acc[k][3] : 0.0f;
        *reinterpret_cast<float4*>(om + gy * IMG_W + gxb) = v;
    }
}

extern "C" void kernel_launch(void* const* d_in, const int* in_sizes, int n_in,
                              void* d_out, int out_size) {
    const float* in = (const float*)d_in[0];
    float* out = (float*)d_out;
    dim3 block(TX, TYB, 1);
    dim3 grid(IMG_W / BW, IMG_H / BH, 96);   // 8 x 4 x 96 = 3072 blocks
    soft_hist_kernel<<<grid, block>>>(in, out);
}

// round 16
// speedup vs baseline: 1.0234x; 1.0234x over previous
#include <cuda_runtime.h>
#include <cuda_bf16.h>

// Soft local histogram, R=5, bandwidth=0.5.
// Input/output: (4, 8, 3, 256, 256) fp32 -> 96 images of 256x256.
// out[y,x] = sum_{di,dj in [-2,2]} max(0, 1 - 2*|x[y+di,x+dj] - x[y,x]|)
// for y,x in [2, 254); zero on the 2-pixel border.
//
// Tap math (R15 hybrid, 5 issues / 2 taps):
//   d2      = fma.rn.f32x2(a_pair, {2,2}, nc2_pair)   // pairs free from LDS
//   w_lo/hi = __saturatef(fma(|d|, -1, 1))            // FFMA.SAT-imm
//   acc     += scalar FFMA-imm
// This round trims overhead: shift-only halo addressing (no div by 12) and
// hoisted x-border mask in the epilogue.

#define IMG_H 256
#define IMG_W 256
#define TX 8            // threads in x; each covers PX=4 pixels -> 32 wide
#define TYB 32
#define PX 4
#define PY 2
#define BW 32
#define BH (TYB * PY)   // 64 output rows per block
#define TILE_H (BH + 4) // 68
#define TILE_W 56

typedef unsigned long long u64;

__device__ __forceinline__ u64 ffma2(u64 a, u64 b, u64 c) {
    u64 d;
    asm("fma.rn.f32x2 %0, %1, %2, %3;" : "=l"(d) : "l"(a), "l"(b), "l"(c));
    return d;
}
__device__ __forceinline__ u64 fmul2(u64 a, u64 b) {
    u64 d;
    asm("mul.rn.f32x2 %0, %1, %2;" : "=l"(d) : "l"(a), "l"(b));
    return d;
}
__device__ __forceinline__ u64 pack2(float lo, float hi) {
    u64 r;
    asm("mov.b64 %0, {%1, %2};" : "=l"(r) : "f"(lo), "f"(hi));
    return r;
}
__device__ __forceinline__ void unpack2(u64 v, float& lo, float& hi) {
    asm("mov.b64 {%0, %1}, %2;" : "=f"(lo), "=f"(hi) : "l"(v));
}

#define TWO2  0x4000000040000000ull   // {2.0f, 2.0f}
#define NTWO2 0xC0000000C0000000ull   // {-2.0f, -2.0f}

__global__ __launch_bounds__(TX * TYB, 6) void soft_hist_kernel(
    const float* __restrict__ in, float* __restrict__ out)
{
    __shared__ float tile[TILE_H][TILE_W];

    const int img = blockIdx.z;
    const float* im = in + (size_t)img * IMG_H * IMG_W;
    float* om = out + (size_t)img * IMG_H * IMG_W;

    const int x0 = blockIdx.x * BW;
    const int y0 = blockIdx.y * BH;
    const int tx = threadIdx.x;
    const int ty = threadIdx.y;
    const int tid = ty * TX + tx;

    // 48-float aligned load window from base_x; smem col s = g - base_x + 4.
    // Clamped rows/cols only feed outputs in the forced-zero border.
    int base_x = x0 - 8;
    if (base_x < 0) base_x = 0;
    if (base_x > IMG_W - 48) base_x = IMG_W - 48;   // 208

    // Halo load, shift-only addressing.
    // Wave 1: rows 0..63, each thread moves 3 float4s (cols (tid&3) + 4q).
    {
        int ly = tid >> 2;                     // 0..63
        int lf = tid & 3;
        int gy = min(max(y0 + ly - 2, 0), IMG_H - 1);
        const float4* src = reinterpret_cast<const float4*>(im + gy * IMG_W + base_x);
        float4* dst = reinterpret_cast<float4*>(&tile[ly][4]);
        #pragma unroll
        for (int q = 0; q < 3; q++)
            dst[lf + 4 * q] = src[lf + 4 * q];
    }
    // Wave 2: rows 64..67 (4 rows x 12 float4s), threads 0..63, cols tid&15.
    if (tid < 64) {
        int ly = 64 + (tid >> 4);              // 64..67
        int lf = tid & 15;
        if (lf < 12) {
            int gy = min(max(y0 + ly - 2, 0), IMG_H - 1);
            reinterpret_cast<float4*>(&tile[ly][4])[lf] =
                reinterpret_cast<const float4*>(im + gy * IMG_W + base_x)[lf];
        }
    }
    __syncthreads();

    // Thread outputs: cols gxb + p (p=0..3), rows y0 + ty*PY + k (k=0..1).
    const int scol0 = (x0 + PX * tx) - base_x + 4;
    const int rbase = ty * PY;

    // Centers: LDS.128 -> two aligned pairs -> nc2 pairs via mul.f32x2.
    u64 nc2p[PY][2];         // [k][h]: (-2c_{2h}, -2c_{2h+1})
    float acc[PY][PX];       // scalar 2*sum accumulators (center included:
                             //  fma(c,2,-2c) == 0 -> w == 1 exactly)
    #pragma unroll
    for (int k = 0; k < PY; k++) {
        ulonglong2 c = *reinterpret_cast<const ulonglong2*>(&tile[rbase + k + 2][scol0]);
        nc2p[k][0] = fmul2(c.x, NTWO2);
        nc2p[k][1] = fmul2(c.y, NTWO2);
        #pragma unroll
        for (int p = 0; p < PX; p++) acc[k][p] = 0.0f;
    }

    // Slide over PY+4 tap rows. Row window a[0..7], a[i] at col scol0-2+i.
    // Packed pairs P[i] = (a[i], a[i+1]); pair h taps j use P[j + 2h].
    #pragma unroll
    for (int ry = 0; ry < PY + 4; ry++) {
        const float* row = &tile[rbase + ry][0];
        u64 P[7];
        P[0] = *reinterpret_cast<const u64*>(row + scol0 - 2);          // (a0,a1)
        {
            ulonglong2 md = *reinterpret_cast<const ulonglong2*>(row + scol0);
            P[2] = md.x;                                                // (a2,a3)
            P[4] = md.y;                                                // (a4,a5)
        }
        P[6] = *reinterpret_cast<const u64*>(row + scol0 + 4);          // (a6,a7)
        {
            float a0, a1, a2, a3, a4, a5, a6, a7;
            unpack2(P[0], a0, a1);
            unpack2(P[2], a2, a3);
            unpack2(P[4], a4, a5);
            unpack2(P[6], a6, a7);
            P[1] = pack2(a1, a2);
            P[3] = pack2(a3, a4);
            P[5] = pack2(a5, a6);
        }
        #pragma unroll
        for (int k = 0; k < PY; k++) {
            if (ry >= k && ry <= k + 4) {
                #pragma unroll
                for (int h = 0; h < 2; h++) {
                    #pragma unroll
                    for (int j = 0; j < 5; j++) {
                        u64 d2 = ffma2(P[j + 2 * h], TWO2, nc2p[k][h]);   // 2 taps
                        float dlo, dhi;
                        unpack2(d2, dlo, dhi);
                        float wlo = __saturatef(fmaf(fabsf(dlo), -1.0f, 1.0f));
                        float whi = __saturatef(fmaf(fabsf(dhi), -1.0f, 1.0f));
                        acc[k][2 * h + 0] = fmaf(wlo, 2.0f, acc[k][2 * h + 0]);
                        acc[k][2 * h + 1] = fmaf(whi, 2.0f, acc[k][2 * h + 1]);
                    }
                }
            }
        }
    }

    // Epilogue: hoisted x-border mask (0.5 or 0), per-row y predicate,
    // one STG.128 per output row.
    const int gxb = x0 + PX * tx;
    float m0 = (gxb + 0 >= 2 && gxb + 0 < IMG_W - 2) ? 0.5f : 0.0f;
    float m1 = (gxb + 1 >= 2 && gxb + 1 < IMG_W - 2) ? 0.5f : 0.0f;
    float m2 = (gxb + 2 >= 2 && gxb + 2 < IMG_W - 2) ? 0.5f : 0.0f;
    float m3 = (gxb + 3 >= 2 && gxb + 3 < IMG_W - 2) ? 0.5f : 0.0f;
    #pragma unroll
    for (int k = 0; k < PY; k++) {
        int gy = y0 + rbase + k;
        float ym = (gy >= 2 && gy < IMG_H - 2) ? 1.0f : 0.0f;
        float4 v;
        v.x = (m0 * ym) * acc[k][0];
        v.y = (m1 * ym) * acc[k][1];
        v.z = (m2 * ym) * acc[k][2];
        v.w = (m3 * ym) * acc[k][3];
        *reinterpret_cast<float4*>(om + gy * IMG_W + gxb) = v;
    }
}

extern "C" void kernel_launch(void* const* d_in, const int* in_sizes, int n_in,
                              void* d_out, int out_size) {
    const float* in = (const float*)d_in[0];
    float* out = (float*)d_out;
    dim3 block(TX, TYB, 1);
    dim3 grid(IMG_W / BW, IMG_H / BH, 96);   // 8 x 4 x 96 = 3072 blocks
    soft_hist_kernel<<<grid, block>>>(in, out);
}

// round 17
// speedup vs baseline: 1.1130x; 1.0876x over previous
#include <cuda_runtime.h>
#include <cuda_bf16.h>
#include <cstring>

// Soft local histogram, R=5, bandwidth=0.5.
// Input/output: (4, 8, 3, 256, 256) fp32 -> 96 images of 256x256.
// out[y,x] = sum_{di,dj in [-2,2]} max(0, 1 - 2*|x[y+di,x+dj] - x[y,x]|)
// for y,x in [2, 254); zero on the 2-pixel border.
//
// Parity-split taps, zero forced register shuffles:
//  - even j (0,2,4): packed FFMA2 on pairs that ARE the aligned LDS results
//    (lo, md.xy, md.zw, hi) -> 5 issues / 2 taps, no packing.
//  - odd j (1,3): scalar 3x FFMA-imm reading load components directly.
//  2.7 issues/tap vs 3.0 scalar, without R14-16's mov.b64 pack/unpack tax.
// Center tap falls in packed path: fma(c,2,-2c) == 0 -> w == 1 exactly.

#define IMG_H 256
#define IMG_W 256
#define TX 8            // threads in x; each covers PX=4 pixels -> 32 wide
#define TYB 32
#define PX 4
#define PY 2
#define BW 32
#define BH (TYB * PY)   // 64 output rows per block
#define TILE_H (BH + 4) // 68
#define TILE_W 56

typedef unsigned long long u64;

__device__ __forceinline__ u64 ffma2(u64 a, u64 b, u64 c) {
    u64 d;
    asm("fma.rn.f32x2 %0, %1, %2, %3;" : "=l"(d) : "l"(a), "l"(b), "l"(c));
    return d;
}
__device__ __forceinline__ u64 f2_as_u64(float lo, float hi) {
    float2 v = make_float2(lo, hi);
    u64 r; memcpy(&r, &v, 8); return r;
}
__device__ __forceinline__ float2 u64_as_f2(u64 v) {
    float2 r; memcpy(&r, &v, 8); return r;
}

#define TWO2 0x4000000040000000ull   // {2.0f, 2.0f}

__global__ __launch_bounds__(TX * TYB, 6) void soft_hist_kernel(
    const float* __restrict__ in, float* __restrict__ out)
{
    __shared__ float tile[TILE_H][TILE_W];

    const int img = blockIdx.z;
    const float* im = in + (size_t)img * IMG_H * IMG_W;
    float* om = out + (size_t)img * IMG_H * IMG_W;

    const int x0 = blockIdx.x * BW;
    const int y0 = blockIdx.y * BH;
    const int tx = threadIdx.x;
    const int ty = threadIdx.y;
    const int tid = ty * TX + tx;

    // 48-float aligned load window from base_x; smem col s = g - base_x + 4.
    // Clamped rows/cols only feed outputs in the forced-zero border.
    int base_x = x0 - 8;
    if (base_x < 0) base_x = 0;
    if (base_x > IMG_W - 48) base_x = IMG_W - 48;   // 208

    // Halo load, shift-only addressing (R16).
    {
        int ly = tid >> 2;                     // 0..63
        int lf = tid & 3;
        int gy = min(max(y0 + ly - 2, 0), IMG_H - 1);
        const float4* src = reinterpret_cast<const float4*>(im + gy * IMG_W + base_x);
        float4* dst = reinterpret_cast<float4*>(&tile[ly][4]);
        #pragma unroll
        for (int q = 0; q < 3; q++)
            dst[lf + 4 * q] = src[lf + 4 * q];
    }
    if (tid < 64) {
        int ly = 64 + (tid >> 4);              // 64..67
        int lf = tid & 15;
        if (lf < 12) {
            int gy = min(max(y0 + ly - 2, 0), IMG_H - 1);
            reinterpret_cast<float4*>(&tile[ly][4])[lf] =
                reinterpret_cast<const float4*>(im + gy * IMG_W + base_x)[lf];
        }
    }
    __syncthreads();

    // Thread outputs: cols gxb + p (p=0..3), rows y0 + ty*PY + k (k=0..1).
    const int scol0 = (x0 + PX * tx) - base_x + 4;
    const int rbase = ty * PY;

    // Centers: scalar -2c values, then pairs packed once (amortized).
    float nc2s[PY][PX];
    u64 nc2p[PY][2];
    float acc[PY][PX];
    #pragma unroll
    for (int k = 0; k < PY; k++) {
        float4 c = *reinterpret_cast<const float4*>(&tile[rbase + k + 2][scol0]);
        nc2s[k][0] = -2.0f * c.x;
        nc2s[k][1] = -2.0f * c.y;
        nc2s[k][2] = -2.0f * c.z;
        nc2s[k][3] = -2.0f * c.w;
        nc2p[k][0] = f2_as_u64(nc2s[k][0], nc2s[k][1]);
        nc2p[k][1] = f2_as_u64(nc2s[k][2], nc2s[k][3]);
        #pragma unroll
        for (int p = 0; p < PX; p++) acc[k][p] = 0.0f;
    }

    // Slide over PY+4 tap rows. a[i] at col scol0-2+i; tap (k,p,j) -> a[p+j].
    #pragma unroll
    for (int ry = 0; ry < PY + 4; ry++) {
        const float* row = &tile[rbase + ry][0];
        float2 lo = *reinterpret_cast<const float2*>(row + scol0 - 2);  // a0,a1
        float4 md = *reinterpret_cast<const float4*>(row + scol0);      // a2..a5
        float2 hi = *reinterpret_cast<const float2*>(row + scol0 + 4);  // a6,a7
        // Even pairs ARE the load halves — no shuffling.
        u64 Pe[4];
        Pe[0] = f2_as_u64(lo.x, lo.y);   // (a0,a1)
        Pe[1] = f2_as_u64(md.x, md.y);   // (a2,a3)
        Pe[2] = f2_as_u64(md.z, md.w);   // (a4,a5)
        Pe[3] = f2_as_u64(hi.x, hi.y);   // (a6,a7)
        float a[8] = {lo.x, lo.y, md.x, md.y, md.z, md.w, hi.x, hi.y};

        #pragma unroll
        for (int k = 0; k < PY; k++) {
            if (ry >= k && ry <= k + 4) {
                // Even j: packed. Group (h, j) covers taps p=2h, 2h+1.
                #pragma unroll
                for (int h = 0; h < 2; h++) {
                    #pragma unroll
                    for (int je = 0; je < 3; je++) {          // j = 2*je
                        u64 d2 = ffma2(Pe[je + h], TWO2, nc2p[k][h]);
                        float2 d = u64_as_f2(d2);
                        float wlo = __saturatef(fmaf(fabsf(d.x), -1.0f, 1.0f));
                        float whi = __saturatef(fmaf(fabsf(d.y), -1.0f, 1.0f));
                        acc[k][2 * h + 0] = fmaf(wlo, 2.0f, acc[k][2 * h + 0]);
                        acc[k][2 * h + 1] = fmaf(whi, 2.0f, acc[k][2 * h + 1]);
                    }
                }
                // Odd j: scalar, direct component reads.
                #pragma unroll
                for (int jo = 0; jo < 2; jo++) {              // j = 1, 3
                    const int j = 1 + 2 * jo;
                    #pragma unroll
                    for (int p = 0; p < PX; p++) {
                        float d = fmaf(a[p + j], 2.0f, nc2s[k][p]);        // FFMA-imm
                        float w = __saturatef(fmaf(fabsf(d), -1.0f, 1.0f)); // FFMA.SAT
                        acc[k][p] = fmaf(w, 2.0f, acc[k][p]);              // FFMA-imm
                    }
                }
            }
        }
    }

    // Epilogue: hoisted x-border mask, per-row y predicate, STG.128 per row.
    const int gxb = x0 + PX * tx;
    float m0 = (gxb + 0 >= 2 && gxb + 0 < IMG_W - 2) ? 0.5f : 0.0f;
    float m1 = (gxb + 1 >= 2 && gxb + 1 < IMG_W - 2) ? 0.5f : 0.0f;
    float m2 = (gxb + 2 >= 2 && gxb + 2 < IMG_W - 2) ? 0.5f : 0.0f;
    float m3 = (gxb + 3 >= 2 && gxb + 3 < IMG_W - 2) ? 0.5f : 0.0f;
    #pragma unroll
    for (int k = 0; k < PY; k++) {
        int gy = y0 + rbase + k;
        float ym = (gy >= 2 && gy < IMG_H - 2) ? 1.0f : 0.0f;
        float4 v;
        v.x = (m0 * ym) * acc[k][0];
        v.y = (m1 * ym) * acc[k][1];
        v.z = (m2 * ym) * acc[k][2];
        v.w = (m3 * ym) * acc[k][3];
        *reinterpret_cast<float4*>(om + gy * IMG_W + gxb) = v;
    }
}

extern "C" void kernel_launch(void* const* d_in, const int* in_sizes, int n_in,
                              void* d_out, int out_size) {
    const float* in = (const float*)d_in[0];
    float* out = (float*)d_out;
    dim3 block(TX, TYB, 1);
    dim3 grid(IMG_W / BW, IMG_H / BH, 96);   // 8 x 4 x 96 = 3072 blocks
    soft_hist_kernel<<<grid, block>>>(in, out);
}